// round 1
// baseline (speedup 1.0000x reference)
#include <cuda_runtime.h>

#define NN 64
#define SS 60
#define GG 180
#define BATCH 512
#define SEX 10
#define ROWS 4
#define NT 192
#define NBLK (BATCH/ROWS)
#define NACT 5
#define NROLE 7
#define OO 8
#define II 8

// ---- shared memory layout (float offsets) ----
#define OFF_WHHF 0
#define OFF_WHHB 10800
#define OFF_WIHF 21600
#define OFF_WIHB 32400
#define OFF_WFT  43200
#define OFF_WBT  48000
#define OFF_BHHF 52800
#define OFF_BHHB 52980
#define OFF_BIHF 53160
#define OFF_BIHB 53340
#define OFF_BF   53520
#define OFF_BBIAS 53580
#define OFF_HAS  53640
#define OFF_WU   53896
#define OFF_H4   54736
#define OFF_RHO4 54976
#define OFF_S4   55216
#define OFF_AF   56176
#define OFF_ZI   56416
#define OFF_DZI  56456
#define OFF_OMG  56496
#define OFF_MASKP 56520
#define OFF_MASKS 56648
#define SMEM_FLOATS 56776
#define SMEM_BYTES (SMEM_FLOATS * 4)

// ---- global scratch (per-batch-row private; no cross-block sharing) ----
__device__ float g_rho_f[(size_t)NN * BATCH * SS];
__device__ float g_rho_b[(size_t)NN * BATCH * SS];
__device__ float g_gi_f[(size_t)NN * BATCH * GG];
__device__ float g_gi_b[(size_t)NN * BATCH * GG];

__device__ __forceinline__ float sigm(float x) {
    return __fdividef(1.f, 1.f + __expf(-x));
}
__device__ __forceinline__ float tanh_f(float x) {
    float e = __expf(2.f * x);
    return 1.f - __fdividef(2.f, e + 1.f);
}

// One blended GRU step: h <- h + blend_j * (GRU(gi[node], h) - h)
// blend = has[:, node] (adj bit already tested by caller).
__device__ __forceinline__ void gru_step(int node, const float* gi_g,
                                         int wtOff, int bhhOff,
                                         bool& hzero, int row0)
{
    extern __shared__ float sm[];
    const int t = threadIdx.x;
    if (t < GG) {
        const float* gib = gi_g + ((size_t)node * BATCH + row0) * GG + t;
        float g0 = gib[0];
        float g1 = gib[GG];
        float g2 = gib[2 * GG];
        float g3 = gib[3 * GG];
        float a0 = 0.f, a1 = 0.f, a2 = 0.f, a3 = 0.f;
        if (!hzero) {
#pragma unroll
            for (int s = 0; s < SS; s++) {
                float w = sm[wtOff + s * GG + t];
                float4 h = *(const float4*)&sm[OFF_H4 + s * 4];
                a0 = fmaf(w, h.x, a0);
                a1 = fmaf(w, h.y, a1);
                a2 = fmaf(w, h.z, a2);
                a3 = fmaf(w, h.w, a3);
            }
        }
        float bh = sm[bhhOff + t];
        if (t < 2 * SS) {
            // r/z gate pre-activations: gi + gh + bhh (gi already has bih)
            *(float4*)&sm[OFF_S4 + t * 4] =
                make_float4(a0 + bh + g0, a1 + bh + g1, a2 + bh + g2, a3 + bh + g3);
        } else {
            // n gate: keep gh_n (+bhh) and gi_n separate (n = tanh(gi_n + r*gh_n))
            *(float4*)&sm[OFF_S4 + t * 4] =
                make_float4(a0 + bh, a1 + bh, a2 + bh, a3 + bh);
            *(float4*)&sm[OFF_S4 + (t + SS) * 4] = make_float4(g0, g1, g2, g3);
        }
    }
    __syncthreads();
    for (int idx = t; idx < SS * ROWS; idx += NT) {
        int b = idx & 3;
        float r  = sigm(sm[OFF_S4 + idx]);
        float zg = sigm(sm[OFF_S4 + SS * ROWS + idx]);
        float nv = tanh_f(fmaf(r, sm[OFF_S4 + 2 * SS * ROWS + idx],
                               sm[OFF_S4 + 3 * SS * ROWS + idx]));
        float hold = hzero ? 0.f : sm[OFF_H4 + idx];
        float hnew = (1.f - zg) * nv + zg * hold;
        float blend = sm[OFF_HAS + b * NN + node];
        sm[OFF_H4 + idx] = hold + blend * (hnew - hold);
    }
    __syncthreads();
    hzero = false;
}

// rho_i = act( [h, z_i, dz_i] @ W^T + bias ), written to smem (transposed) + global
__device__ __forceinline__ void project(int node, const float* zg, const float* dzg,
                                        int wftOff, int bOff, float* rho_g,
                                        bool isfwd, bool hzero, int row0)
{
    extern __shared__ float sm[];
    const int t = threadIdx.x;
    if (t < ROWS * SEX) {
        int b = t / SEX, u = t % SEX;
        size_t base = ((size_t)(row0 + b)) * NN * SEX + (size_t)node * SEX + u;
        sm[OFF_ZI + t]  = zg[base];
        sm[OFF_DZI + t] = dzg[base];
    }
    __syncthreads();
    for (int idx = t; idx < SS * ROWS; idx += NT) {
        int o = idx >> 2, b = idx & 3;
        float acc = sm[bOff + o];
        if (!hzero) {
#pragma unroll
            for (int s = 0; s < SS; s++)
                acc = fmaf(sm[wftOff + s * SS + o], sm[OFF_H4 + s * 4 + b], acc);
        }
#pragma unroll
        for (int u = 0; u < SEX; u++) {
            acc = fmaf(sm[wftOff + (SS + u) * SS + o], sm[OFF_ZI + b * SEX + u], acc);
            acc = fmaf(sm[wftOff + (SS + SEX + u) * SS + o], sm[OFF_DZI + b * SEX + u], acc);
        }
        float v = isfwd ? tanh_f(acc) : acc;
        sm[OFF_RHO4 + idx] = v;
        rho_g[((size_t)node * BATCH + row0 + b) * SS + o] = v;
    }
    __syncthreads();
}

// gi[node] = rho[node] @ Wih^T + bih  (precompute; reused per out-edge)
__device__ __forceinline__ void gi_step(int node, float* gi_g,
                                        int wihtOff, int bihOff, int row0)
{
    extern __shared__ float sm[];
    const int t = threadIdx.x;
    if (t < GG) {
        float bi = sm[bihOff + t];
        float a0 = bi, a1 = bi, a2 = bi, a3 = bi;
#pragma unroll
        for (int s = 0; s < SS; s++) {
            float w = sm[wihtOff + s * GG + t];
            float4 r = *(const float4*)&sm[OFF_RHO4 + s * 4];
            a0 = fmaf(w, r.x, a0);
            a1 = fmaf(w, r.y, a1);
            a2 = fmaf(w, r.z, a2);
            a3 = fmaf(w, r.w, a3);
        }
        float* gb = gi_g + ((size_t)node * BATCH + row0) * GG + t;
        gb[0] = a0; gb[GG] = a1; gb[2 * GG] = a2; gb[3 * GG] = a3;
    }
    __syncthreads();
}

__global__ void __launch_bounds__(NT, 1)
designer_kernel(const float* z, const float* dz, const float* has, const int* adj,
                const float* Wih_f, const float* Whh_f, const float* bih_f, const float* bhh_f,
                const float* Wih_b, const float* Whh_b, const float* bih_b, const float* bhh_b,
                const float* Wf, const float* bf, const float* Wb, const float* bb,
                const float* Wa, const float* ba, const float* Wc, const float* bc,
                const float* Wu, const float* bu, float* out)
{
    extern __shared__ float sm[];
    const int t = threadIdx.x;
    const int row0 = blockIdx.x * ROWS;

    // ---- stage weights (transposed) + biases + has + adjacency bitmasks ----
    for (int idx = t; idx < GG * SS; idx += NT) {
        int k = idx / SS, s = idx % SS;
        sm[OFF_WHHF + s * GG + k] = Whh_f[idx];
        sm[OFF_WHHB + s * GG + k] = Whh_b[idx];
        sm[OFF_WIHF + s * GG + k] = Wih_f[idx];
        sm[OFF_WIHB + s * GG + k] = Wih_b[idx];
    }
    for (int idx = t; idx < SS * (SS + 2 * SEX); idx += NT) {
        int o = idx / (SS + 2 * SEX), c = idx % (SS + 2 * SEX);
        sm[OFF_WFT + c * SS + o] = Wf[idx];
        sm[OFF_WBT + c * SS + o] = Wb[idx];
    }
    for (int idx = t; idx < GG; idx += NT) {
        sm[OFF_BHHF + idx] = bhh_f[idx];
        sm[OFF_BHHB + idx] = bhh_b[idx];
        sm[OFF_BIHF + idx] = bih_f[idx];
        sm[OFF_BIHB + idx] = bih_b[idx];
    }
    if (t < SS) { sm[OFF_BF + t] = bf[t]; sm[OFF_BBIAS + t] = bb[t]; }
    for (int idx = t; idx < ROWS * NN; idx += NT)
        sm[OFF_HAS + idx] = has[(size_t)(row0 + idx / NN) * NN + (idx % NN)];
    for (int idx = t; idx < NROLE * 2 * SS; idx += NT) sm[OFF_WU + idx] = Wu[idx];
    if (t < NN) {
        unsigned long long pm = 0ull, sk = 0ull;
        for (int j = 0; j < NN; j++) {
            if (adj[j * NN + t]) pm |= 1ull << j;   // predecessors of t (fwd)
            if (adj[t * NN + j]) sk |= 1ull << j;   // successors of t (bwd sources)
        }
        ((unsigned long long*)&sm[OFF_MASKP])[t] = pm;
        ((unsigned long long*)&sm[OFF_MASKS])[t] = sk;
    }
    __syncthreads();

    const unsigned long long* predm = (const unsigned long long*)&sm[OFF_MASKP];
    const unsigned long long* succm = (const unsigned long long*)&sm[OFF_MASKS];

    // ---- forward DAG pass (nodes 0..63 = topological order) ----
    for (int i = 0; i < NN; i++) {
        bool hzero = true;
        unsigned long long m = predm[i];
        while (m) {                                 // ascending j (matches scan order)
            int j = __ffsll((long long)m) - 1;
            m &= m - 1;
            gru_step(j, g_gi_f, OFF_WHHF, OFF_BHHF, hzero, row0);
        }
        project(i, z, dz, OFF_WFT, OFF_BF, g_rho_f, true, hzero, row0);
        if (succm[i] != 0ull || i >= NN - OO)
            gi_step(i, g_gi_f, OFF_WIHF, OFF_BIHF, row0);
    }

    // ---- backward DAG pass (nodes 63..0) ----
    for (int i = NN - 1; i >= 0; i--) {
        bool hzero = true;
        unsigned long long m = succm[i];
        while (m) {                                 // descending j (matches reversed scan)
            int j = 63 - __clzll((long long)m);
            m &= ~(1ull << j);
            gru_step(j, g_gi_b, OFF_WHHB, OFF_BHHB, hzero, row0);
        }
        project(i, z, dz, OFF_WBT, OFF_BBIAS, g_rho_b, false, hzero, row0);
        if (predm[i] != 0ull || i < II)
            gi_step(i, g_gi_b, OFF_WIHB, OFF_BIHB, row0);
    }

    // ---- alpha_f: GRU over nodes 56..63 (blend = has[:, i]) ----
    {
        bool hzero = true;
        for (int i = NN - OO; i < NN; i++)
            gru_step(i, g_gi_f, OFF_WHHF, OFF_BHHF, hzero, row0);
        for (int idx = t; idx < SS * ROWS; idx += NT) sm[OFF_AF + idx] = sm[OFF_H4 + idx];
        __syncthreads();
    }
    // ---- alpha_b: GRU over nodes 7..0 ----
    {
        bool hzero = true;
        for (int i = II - 1; i >= 0; i--)
            gru_step(i, g_gi_b, OFF_WHHB, OFF_BHHB, hzero, row0);
    }

    // ---- heads: omega (B,5) and value (B,1). ab = [alpha_f, alpha_b] ----
    if (t < ROWS * NACT) {
        int b = t / NACT, a = t % NACT;
        float acc = ba[a];
#pragma unroll
        for (int s = 0; s < SS; s++) {
            acc = fmaf(Wa[a * 2 * SS + s],      sm[OFF_AF + s * 4 + b], acc);
            acc = fmaf(Wa[a * 2 * SS + SS + s], sm[OFF_H4 + s * 4 + b], acc);
        }
        sm[OFF_OMG + t] = acc;
    } else if (t < ROWS * NACT + ROWS) {
        int b = t - ROWS * NACT;
        float acc = bc[0];
#pragma unroll
        for (int s = 0; s < SS; s++) {
            acc = fmaf(Wc[s],      sm[OFF_AF + s * 4 + b], acc);
            acc = fmaf(Wc[SS + s], sm[OFF_H4 + s * 4 + b], acc);
        }
        out[(size_t)BATCH * NACT + (size_t)BATCH * NROLE * NN + row0 + b] = acc;
    }
    __syncthreads();
    if (t < ROWS) {
        float mx = -1e30f;
        for (int a = 0; a < NACT; a++) mx = fmaxf(mx, sm[OFF_OMG + t * NACT + a]);
        float e[NACT], ssum = 0.f;
        for (int a = 0; a < NACT; a++) { e[a] = __expf(sm[OFF_OMG + t * NACT + a] - mx); ssum += e[a]; }
        float inv = __fdividef(1.f, ssum);
        for (int a = 0; a < NACT; a++) out[(size_t)(row0 + t) * NACT + a] = e[a] * inv;
    }
    __syncthreads();

    // ---- psi (B,7,64): warp-reduced dots; result overlays Whh_f smem region ----
    {
        int warp = t >> 5, lane = t & 31;
        for (int it = warp; it < ROWS * NROLE * NN; it += NT / 32) {
            int n = it % NN;
            int r = (it / NN) % NROLE;
            int b = it / (NROLE * NN);
            const float* rf = g_rho_f + ((size_t)n * BATCH + row0 + b) * SS;
            const float* rb = g_rho_b + ((size_t)n * BATCH + row0 + b) * SS;
            float p = 0.f;
            for (int s = lane; s < SS; s += 32)
                p += rf[s] * sm[OFF_WU + r * 2 * SS + s] + rb[s] * sm[OFF_WU + r * 2 * SS + SS + s];
#pragma unroll
            for (int o2 = 16; o2; o2 >>= 1) p += __shfl_xor_sync(0xffffffffu, p, o2);
            if (lane == 0) {
                float mval = sm[OFF_HAS + b * NN + n];
                float v = p + bu[r];
                v = mval * v - 60.f * (1.f - mval);
                sm[(b * NROLE + r) * NN + n] = v;   // overlay scratch
            }
        }
    }
    __syncthreads();
    for (int p0 = t; p0 < ROWS * NROLE; p0 += NT) {
        int b = p0 / NROLE, r = p0 % NROLE;
        float* rowp = &sm[(b * NROLE + r) * NN];
        float mx = -1e30f;
        for (int n = 0; n < NN; n++) mx = fmaxf(mx, rowp[n]);
        float ssum = 0.f;
        for (int n = 0; n < NN; n++) { float e = __expf(rowp[n] - mx); rowp[n] = e; ssum += e; }
        float inv = __fdividef(1.f, ssum);
        float* op = out + (size_t)BATCH * NACT + (size_t)(row0 + b) * NROLE * NN + (size_t)r * NN;
        for (int n = 0; n < NN; n++) op[n] = rowp[n] * inv;
    }
}

extern "C" void kernel_launch(void* const* d_in, const int* in_sizes, int n_in,
                              void* d_out, int out_size)
{
    cudaFuncSetAttribute(designer_kernel, cudaFuncAttributeMaxDynamicSharedMemorySize, SMEM_BYTES);
    designer_kernel<<<NBLK, NT, SMEM_BYTES>>>(
        (const float*)d_in[0], (const float*)d_in[1], (const float*)d_in[2], (const int*)d_in[3],
        (const float*)d_in[4], (const float*)d_in[5], (const float*)d_in[6], (const float*)d_in[7],
        (const float*)d_in[8], (const float*)d_in[9], (const float*)d_in[10], (const float*)d_in[11],
        (const float*)d_in[12], (const float*)d_in[13], (const float*)d_in[14], (const float*)d_in[15],
        (const float*)d_in[16], (const float*)d_in[17], (const float*)d_in[18], (const float*)d_in[19],
        (const float*)d_in[20], (const float*)d_in[21], (float*)d_out);
}

// round 3
// speedup vs baseline: 1.2971x; 1.2971x over previous
#include <cuda_runtime.h>

#define NN 64
#define SS 60
#define GG 180
#define BATCH 512
#define SEX 10
#define ROWS 4
#define NT 384
#define NBLK (BATCH/ROWS)
#define NACT 5
#define NROLE 7
#define OO 8
#define II 8

// ---- shared memory layout (float offsets) ----
#define OFF_WHHF 0
#define OFF_WHHB 10800
#define OFF_WIHF 21600
#define OFF_WIHB 32400
#define OFF_WFT  43200
#define OFF_WBT  48000
#define OFF_BHHF 52800
#define OFF_BHHB 52980
#define OFF_BIHF 53160
#define OFF_BIHB 53340
#define OFF_BF   53520
#define OFF_BB   53580
#define OFF_HAS  53640
#define OFF_WU   53896
#define OFF_H4F  54736
#define OFF_H4B  54976
#define OFF_S4F  55216
#define OFF_S4B  56176
#define OFF_RHOF 57136
#define OFF_RHOB 57376
#define OFF_ZIF  57616
#define OFF_DZIF 57656
#define OFF_ZIB  57696
#define OFF_DZIB 57736
#define OFF_OMG  57776
#define OFF_MASKP 57800
#define OFF_MASKS 57928
#define SMEM_FLOATS 58056
#define SMEM_BYTES (SMEM_FLOATS * 4)

// ---- global scratch (per-batch-row private) ----
__device__ float g_rho_f[(size_t)NN * BATCH * SS];
__device__ float g_rho_b[(size_t)NN * BATCH * SS];
__device__ float g_gi_f[(size_t)NN * BATCH * GG];
__device__ float g_gi_b[(size_t)NN * BATCH * GG];

__device__ __forceinline__ float sigm(float x) {
    return __fdividef(1.f, 1.f + __expf(-x));
}
__device__ __forceinline__ float tanh_f(float x) {
    float e = __expf(2.f * x);
    return 1.f - __fdividef(2.f, e + 1.f);
}
__device__ __forceinline__ void fma2(unsigned long long& d, unsigned long long a,
                                     unsigned long long b) {
    asm("fma.rn.f32x2 %0, %1, %2, %0;" : "+l"(d) : "l"(a), "l"(b));
}
__device__ __forceinline__ unsigned long long splat2(float w) {
    unsigned long long r;
    asm("mov.b64 %0, {%1, %1};" : "=l"(r) : "f"(w));
    return r;
}
__device__ __forceinline__ float lo32(unsigned long long v) {
    return __uint_as_float((unsigned)v);
}
__device__ __forceinline__ float hi32(unsigned long long v) {
    return __uint_as_float((unsigned)(v >> 32));
}

// GEMM for one GRU edge, one side. lane in [0,GG).
__device__ __forceinline__ void gemm_side(int node, const float* gi_g, int wOff,
                                          int bhhOff, int hOff, int sOff, bool hz,
                                          int row0, int lane)
{
    extern __shared__ float sm[];
    const float* gib = gi_g + ((size_t)node * BATCH + row0) * GG + lane;
    float g0 = gib[0];
    float g1 = gib[GG];
    float g2 = gib[2 * GG];
    float g3 = gib[3 * GG];
    unsigned long long a01 = 0ull, a23 = 0ull;
    if (!hz) {
#pragma unroll 10
        for (int s = 0; s < SS; s++) {
            unsigned long long wp = splat2(sm[wOff + s * GG + lane]);
            ulonglong2 hh = *(const ulonglong2*)&sm[hOff + s * 4];
            fma2(a01, wp, hh.x);
            fma2(a23, wp, hh.y);
        }
    }
    float a0 = lo32(a01), a1 = hi32(a01), a2 = lo32(a23), a3 = hi32(a23);
    float bh = sm[bhhOff + lane];
    if (lane < 2 * SS) {
        *(float4*)&sm[sOff + lane * 4] =
            make_float4(a0 + bh + g0, a1 + bh + g1, a2 + bh + g2, a3 + bh + g3);
    } else {
        *(float4*)&sm[sOff + lane * 4] =
            make_float4(a0 + bh, a1 + bh, a2 + bh, a3 + bh);
        *(float4*)&sm[sOff + (lane + SS) * 4] = make_float4(g0, g1, g2, g3);
    }
}

__device__ __forceinline__ void act_side(int local, int node, int sOff, int hOff, bool hz)
{
    extern __shared__ float sm[];
    int b = local & 3;
    float r  = sigm(sm[sOff + local]);
    float zg = sigm(sm[sOff + SS * ROWS + local]);
    float nv = tanh_f(fmaf(r, sm[sOff + 2 * SS * ROWS + local],
                           sm[sOff + 3 * SS * ROWS + local]));
    float hold = hz ? 0.f : sm[hOff + local];
    float hnew = (1.f - zg) * nv + zg * hold;
    float blend = sm[OFF_HAS + b * NN + node];
    sm[hOff + local] = hold + blend * (hnew - hold);
}

// Paired GRU step: fwd edge fj (if >=0) and bwd edge bj (if >=0) simultaneously.
__device__ __forceinline__ void gru_pair(int fj, int bj, bool& hzf, bool& hzb, int row0)
{
    const int t = threadIdx.x;
    if (t < GG) {
        if (fj >= 0) gemm_side(fj, g_gi_f, OFF_WHHF, OFF_BHHF, OFF_H4F, OFF_S4F, hzf, row0, t);
    } else if (t >= 192 && t < 192 + GG) {
        if (bj >= 0) gemm_side(bj, g_gi_b, OFF_WHHB, OFF_BHHB, OFF_H4B, OFF_S4B, hzb, row0, t - 192);
    }
    __syncthreads();
    if (t < 240) {
        if (fj >= 0) act_side(t, fj, OFF_S4F, OFF_H4F, hzf);
    } else {
        if (bj >= 0) act_side(t - 240, bj, OFF_S4B, OFF_H4B, hzb);
    }
    if (t < 480 - NT) {
        if (bj >= 0) act_side(t + NT - 240, bj, OFF_S4B, OFF_H4B, hzb);
    }
    __syncthreads();
    if (fj >= 0) hzf = false;
    if (bj >= 0) hzb = false;
}

// Paired projection: rho_f[fi] (tanh) and rho_b[bi] (linear).
__device__ __forceinline__ void project_pair(int fi, int bi, bool hzf, bool hzb,
                                             const float* z, const float* dz, int row0)
{
    extern __shared__ float sm[];
    const int t = threadIdx.x;
    if (t < 160) {
        int which = t / 40;           // 0 zF 1 dzF 2 zB 3 dzB
        int loc = t % 40;
        int b = loc / SEX, u = loc % SEX;
        int node = (which < 2) ? fi : bi;
        const float* src = (which & 1) ? dz : z;
        int dst = (which == 0) ? OFF_ZIF : (which == 1) ? OFF_DZIF
                : (which == 2) ? OFF_ZIB : OFF_DZIB;
        sm[dst + loc] = src[((size_t)(row0 + b)) * NN * SEX + (size_t)node * SEX + u];
    }
    __syncthreads();
    for (int idx = t; idx < 480; idx += NT) {
        bool isF = idx < 240;
        int local = isF ? idx : idx - 240;
        int o = local >> 2, b = local & 3;
        int wOff  = isF ? OFF_WFT : OFF_WBT;
        int hOff  = isF ? OFF_H4F : OFF_H4B;
        int ziOff = isF ? OFF_ZIF : OFF_ZIB;
        int dziOff = isF ? OFF_DZIF : OFF_DZIB;
        bool hz = isF ? hzf : hzb;
        float acc = sm[(isF ? OFF_BF : OFF_BB) + o];
        if (!hz) {
#pragma unroll 10
            for (int s = 0; s < SS; s++)
                acc = fmaf(sm[wOff + s * SS + o], sm[hOff + s * 4 + b], acc);
        }
#pragma unroll
        for (int u = 0; u < SEX; u++) {
            acc = fmaf(sm[wOff + (SS + u) * SS + o], sm[ziOff + b * SEX + u], acc);
            acc = fmaf(sm[wOff + (SS + SEX + u) * SS + o], sm[dziOff + b * SEX + u], acc);
        }
        float v = isF ? tanh_f(acc) : acc;
        sm[(isF ? OFF_RHOF : OFF_RHOB) + local] = v;
        float* rg = isF ? g_rho_f : g_rho_b;
        int node = isF ? fi : bi;
        rg[((size_t)node * BATCH + row0 + b) * SS + o] = v;
    }
    __syncthreads();
}

__device__ __forceinline__ void gi_side(int node, float* gi_g, int wOff, int bihOff,
                                        int rhoOff, int row0, int lane)
{
    extern __shared__ float sm[];
    unsigned long long a01 = splat2(sm[bihOff + lane]);
    unsigned long long a23 = a01;
#pragma unroll 10
    for (int s = 0; s < SS; s++) {
        unsigned long long wp = splat2(sm[wOff + s * GG + lane]);
        ulonglong2 rr = *(const ulonglong2*)&sm[rhoOff + s * 4];
        fma2(a01, wp, rr.x);
        fma2(a23, wp, rr.y);
    }
    float* gb = gi_g + ((size_t)node * BATCH + row0) * GG + lane;
    gb[0] = lo32(a01);
    gb[GG] = hi32(a01);
    gb[2 * GG] = lo32(a23);
    gb[3 * GG] = hi32(a23);
}

__device__ __forceinline__ void gi_pair(int fi, int bi, bool doF, bool doB, int row0)
{
    const int t = threadIdx.x;
    if (t < GG) {
        if (doF) gi_side(fi, g_gi_f, OFF_WIHF, OFF_BIHF, OFF_RHOF, row0, t);
    } else if (t >= 192 && t < 192 + GG) {
        if (doB) gi_side(bi, g_gi_b, OFF_WIHB, OFF_BIHB, OFF_RHOB, row0, t - 192);
    }
    __syncthreads();
}

__global__ void __launch_bounds__(NT, 1)
designer_kernel(const float* z, const float* dz, const float* has, const int* adj,
                const float* Wih_f, const float* Whh_f, const float* bih_f, const float* bhh_f,
                const float* Wih_b, const float* Whh_b, const float* bih_b, const float* bhh_b,
                const float* Wf, const float* bf, const float* Wb, const float* bb,
                const float* Wa, const float* ba, const float* Wc, const float* bc,
                const float* Wu, const float* bu, float* out)
{
    extern __shared__ float sm[];
    const int t = threadIdx.x;
    const int row0 = blockIdx.x * ROWS;

    // ---- stage weights (transposed) + biases + has + adjacency bitmasks ----
    for (int idx = t; idx < GG * SS; idx += NT) {
        int k = idx / SS, s = idx % SS;
        sm[OFF_WHHF + s * GG + k] = Whh_f[idx];
        sm[OFF_WHHB + s * GG + k] = Whh_b[idx];
        sm[OFF_WIHF + s * GG + k] = Wih_f[idx];
        sm[OFF_WIHB + s * GG + k] = Wih_b[idx];
    }
    for (int idx = t; idx < SS * (SS + 2 * SEX); idx += NT) {
        int o = idx / (SS + 2 * SEX), c = idx % (SS + 2 * SEX);
        sm[OFF_WFT + c * SS + o] = Wf[idx];
        sm[OFF_WBT + c * SS + o] = Wb[idx];
    }
    for (int idx = t; idx < GG; idx += NT) {
        sm[OFF_BHHF + idx] = bhh_f[idx];
        sm[OFF_BHHB + idx] = bhh_b[idx];
        sm[OFF_BIHF + idx] = bih_f[idx];
        sm[OFF_BIHB + idx] = bih_b[idx];
    }
    if (t < SS) { sm[OFF_BF + t] = bf[t]; sm[OFF_BB + t] = bb[t]; }
    for (int idx = t; idx < ROWS * NN; idx += NT)
        sm[OFF_HAS + idx] = has[(size_t)(row0 + idx / NN) * NN + (idx % NN)];
    for (int idx = t; idx < NROLE * 2 * SS; idx += NT) sm[OFF_WU + idx] = Wu[idx];
    if (t < NN) {
        unsigned long long pm = 0ull, sk = 0ull;
        for (int j = 0; j < NN; j++) {
            if (adj[j * NN + t]) pm |= 1ull << j;   // predecessors (fwd)
            if (adj[t * NN + j]) sk |= 1ull << j;   // successors (bwd)
        }
        ((unsigned long long*)&sm[OFF_MASKP])[t] = pm;
        ((unsigned long long*)&sm[OFF_MASKS])[t] = sk;
    }
    __syncthreads();

    const unsigned long long* predm = (const unsigned long long*)&sm[OFF_MASKP];
    const unsigned long long* succm = (const unsigned long long*)&sm[OFF_MASKS];

    // ---- paired DAG passes: fwd target i, bwd target 63-i ----
    for (int i = 0; i < NN; i++) {
        const int fi = i, bi = NN - 1 - i;
        bool hzf = true, hzb = true;
        unsigned long long mf = predm[fi];
        unsigned long long mb = succm[bi];
        while (mf | mb) {
            int fj = -1, bj = -1;
            if (mf) { fj = __ffsll((long long)mf) - 1; mf &= mf - 1; }            // ascending
            if (mb) { bj = 63 - __clzll((long long)mb); mb &= ~(1ull << bj); }    // descending
            gru_pair(fj, bj, hzf, hzb, row0);
        }
        project_pair(fi, bi, hzf, hzb, z, dz, row0);
        bool doF = (succm[fi] != 0ull) || (fi >= NN - OO);
        bool doB = (predm[bi] != 0ull) || (bi < II);
        gi_pair(fi, bi, doF, doB, row0);
    }

    // ---- paired alpha scans: alpha_f over 56..63 (fwd), alpha_b over 7..0 (bwd) ----
    {
        bool hzf = true, hzb = true;
        for (int k = 0; k < OO; k++)
            gru_pair(NN - OO + k, II - 1 - k, hzf, hzb, row0);
    }
    // alpha_f now lives in H4F, alpha_b in H4B

    // ---- heads: omega (B,5) and value (B,1) ----
    if (t < ROWS * NACT) {
        int b = t / NACT, a = t % NACT;
        float acc = ba[a];
#pragma unroll
        for (int s = 0; s < SS; s++) {
            acc = fmaf(Wa[a * 2 * SS + s],      sm[OFF_H4F + s * 4 + b], acc);
            acc = fmaf(Wa[a * 2 * SS + SS + s], sm[OFF_H4B + s * 4 + b], acc);
        }
        sm[OFF_OMG + t] = acc;
    } else if (t < ROWS * NACT + ROWS) {
        int b = t - ROWS * NACT;
        float acc = bc[0];
#pragma unroll
        for (int s = 0; s < SS; s++) {
            acc = fmaf(Wc[s],      sm[OFF_H4F + s * 4 + b], acc);
            acc = fmaf(Wc[SS + s], sm[OFF_H4B + s * 4 + b], acc);
        }
        out[(size_t)BATCH * NACT + (size_t)BATCH * NROLE * NN + row0 + b] = acc;
    }
    __syncthreads();
    if (t < ROWS) {
        float mx = -1e30f;
        for (int a = 0; a < NACT; a++) mx = fmaxf(mx, sm[OFF_OMG + t * NACT + a]);
        float e[NACT], ssum = 0.f;
        for (int a = 0; a < NACT; a++) {
            e[a] = __expf(sm[OFF_OMG + t * NACT + a] - mx);
            ssum += e[a];
        }
        float inv = __fdividef(1.f, ssum);
        for (int a = 0; a < NACT; a++) out[(size_t)(row0 + t) * NACT + a] = e[a] * inv;
    }
    __syncthreads();

    // ---- psi (B,7,64): warp-reduced dots; scratch overlays Whh_f smem ----
    {
        int warp = t >> 5, lane = t & 31;
        for (int it = warp; it < ROWS * NROLE * NN; it += NT / 32) {
            int n = it % NN;
            int r = (it / NN) % NROLE;
            int b = it / (NROLE * NN);
            const float* rf = g_rho_f + ((size_t)n * BATCH + row0 + b) * SS;
            const float* rb = g_rho_b + ((size_t)n * BATCH + row0 + b) * SS;
            float p = 0.f;
            for (int s = lane; s < SS; s += 32)
                p += rf[s] * sm[OFF_WU + r * 2 * SS + s] + rb[s] * sm[OFF_WU + r * 2 * SS + SS + s];
#pragma unroll
            for (int o2 = 16; o2; o2 >>= 1) p += __shfl_xor_sync(0xffffffffu, p, o2);
            if (lane == 0) {
                float mval = sm[OFF_HAS + b * NN + n];
                float v = p + bu[r];
                v = mval * v - 60.f * (1.f - mval);
                sm[(b * NROLE + r) * NN + n] = v;   // overlay scratch
            }
        }
    }
    __syncthreads();
    for (int p0 = t; p0 < ROWS * NROLE; p0 += NT) {
        int b = p0 / NROLE, r = p0 % NROLE;
        float* rowp = &sm[(b * NROLE + r) * NN];
        float mx = -1e30f;
        for (int n = 0; n < NN; n++) mx = fmaxf(mx, rowp[n]);
        float ssum = 0.f;
        for (int n = 0; n < NN; n++) { float e = __expf(rowp[n] - mx); rowp[n] = e; ssum += e; }
        float inv = __fdividef(1.f, ssum);
        float* op = out + (size_t)BATCH * NACT + (size_t)(row0 + b) * NROLE * NN + (size_t)r * NN;
        for (int n = 0; n < NN; n++) op[n] = rowp[n] * inv;
    }
}

extern "C" void kernel_launch(void* const* d_in, const int* in_sizes, int n_in,
                              void* d_out, int out_size)
{
    cudaFuncSetAttribute(designer_kernel, cudaFuncAttributeMaxDynamicSharedMemorySize, SMEM_BYTES);
    designer_kernel<<<NBLK, NT, SMEM_BYTES>>>(
        (const float*)d_in[0], (const float*)d_in[1], (const float*)d_in[2], (const int*)d_in[3],
        (const float*)d_in[4], (const float*)d_in[5], (const float*)d_in[6], (const float*)d_in[7],
        (const float*)d_in[8], (const float*)d_in[9], (const float*)d_in[10], (const float*)d_in[11],
        (const float*)d_in[12], (const float*)d_in[13], (const float*)d_in[14], (const float*)d_in[15],
        (const float*)d_in[16], (const float*)d_in[17], (const float*)d_in[18], (const float*)d_in[19],
        (const float*)d_in[20], (const float*)d_in[21], (float*)d_out);
}

// round 6
// speedup vs baseline: 1.4844x; 1.1443x over previous
#include <cuda_runtime.h>

#define NN 64
#define SS 60
#define GG 180
#define BATCH 512
#define SEX 10
#define ROWS 4
#define NT 192
#define NACT 5
#define NROLE 7
#define OO 8
#define II 8

// ---- phase-1 shared memory layout (float offsets) ----
#define OFF_WHH 0
#define OFF_WIH 10800
#define OFF_WP  21600
#define OFF_BHH 26400
#define OFF_BIH 26580
#define OFF_BP  26760
#define OFF_HAS 26820
#define OFF_MASK 27076
#define OFF_NEED 27204
#define OFF_H4  27268
#define OFF_S4  27508
#define OFF_RHO 28468
#define OFF_ZI  28708
#define OFF_DZI 28748
#define SMEM_FLOATS 28788
#define SMEM_BYTES (SMEM_FLOATS * 4)

// ---- global scratch ----
__device__ float g_rho_f[(size_t)NN * BATCH * SS];
__device__ float g_rho_b[(size_t)NN * BATCH * SS];
__device__ float g_gi_f[(size_t)NN * BATCH * GG];
__device__ float g_gi_b[(size_t)NN * BATCH * GG];
__device__ float g_alpha_f[(size_t)BATCH * SS];
__device__ float g_alpha_b[(size_t)BATCH * SS];

__device__ __forceinline__ float sigm(float x) {
    return __fdividef(1.f, 1.f + __expf(-x));
}
__device__ __forceinline__ float tanh_f(float x) {
    float e = __expf(2.f * x);
    return 1.f - __fdividef(2.f, e + 1.f);
}
__device__ __forceinline__ void fma2(unsigned long long& d, unsigned long long a,
                                     unsigned long long b) {
    asm("fma.rn.f32x2 %0, %1, %2, %0;" : "+l"(d) : "l"(a), "l"(b));
}
__device__ __forceinline__ unsigned long long splat2(float w) {
    unsigned long long r;
    asm("mov.b64 %0, {%1, %1};" : "=l"(r) : "f"(w));
    return r;
}
__device__ __forceinline__ float lo32(unsigned long long v) {
    return __uint_as_float((unsigned)v);
}
__device__ __forceinline__ float hi32(unsigned long long v) {
    return __uint_as_float((unsigned)(v >> 32));
}

// One blended GRU step in this block's direction.
__device__ __forceinline__ void gru_step(int node, const float* gi_g, bool& hz, int row0)
{
    extern __shared__ float sm[];
    const int t = threadIdx.x;
    if (t < GG) {
        const float* gib = gi_g + ((size_t)node * BATCH + row0) * GG + t;
        float g0 = gib[0];
        float g1 = gib[GG];
        float g2 = gib[2 * GG];
        float g3 = gib[3 * GG];
        unsigned long long a01 = 0ull, a23 = 0ull;
        if (!hz) {
            const float4* wrow = (const float4*)&sm[OFF_WHH + t * SS];
#pragma unroll
            for (int q = 0; q < SS / 4; q++) {
                float4 w4 = wrow[q];
                ulonglong2 h0 = *(const ulonglong2*)&sm[OFF_H4 + (4 * q + 0) * 4];
                ulonglong2 h1 = *(const ulonglong2*)&sm[OFF_H4 + (4 * q + 1) * 4];
                ulonglong2 h2 = *(const ulonglong2*)&sm[OFF_H4 + (4 * q + 2) * 4];
                ulonglong2 h3 = *(const ulonglong2*)&sm[OFF_H4 + (4 * q + 3) * 4];
                unsigned long long wx = splat2(w4.x), wy = splat2(w4.y);
                unsigned long long wz = splat2(w4.z), ww = splat2(w4.w);
                fma2(a01, wx, h0.x); fma2(a23, wx, h0.y);
                fma2(a01, wy, h1.x); fma2(a23, wy, h1.y);
                fma2(a01, wz, h2.x); fma2(a23, wz, h2.y);
                fma2(a01, ww, h3.x); fma2(a23, ww, h3.y);
            }
        }
        float a0 = lo32(a01), a1 = hi32(a01), a2 = lo32(a23), a3 = hi32(a23);
        float bh = sm[OFF_BHH + t];
        if (t < 2 * SS) {
            *(float4*)&sm[OFF_S4 + t * 4] =
                make_float4(a0 + bh + g0, a1 + bh + g1, a2 + bh + g2, a3 + bh + g3);
        } else {
            *(float4*)&sm[OFF_S4 + t * 4] =
                make_float4(a0 + bh, a1 + bh, a2 + bh, a3 + bh);
            *(float4*)&sm[OFF_S4 + (t + SS) * 4] = make_float4(g0, g1, g2, g3);
        }
    }
    __syncthreads();
    for (int idx = t; idx < SS * ROWS; idx += NT) {
        int b = idx & 3;
        float r  = sigm(sm[OFF_S4 + idx]);
        float zg = sigm(sm[OFF_S4 + SS * ROWS + idx]);
        float nv = tanh_f(fmaf(r, sm[OFF_S4 + 2 * SS * ROWS + idx],
                               sm[OFF_S4 + 3 * SS * ROWS + idx]));
        float hold = hz ? 0.f : sm[OFF_H4 + idx];
        float hnew = (1.f - zg) * nv + zg * hold;
        float blend = sm[OFF_HAS + b * NN + node];
        sm[OFF_H4 + idx] = hold + blend * (hnew - hold);
    }
    __syncthreads();
    hz = false;
}

// rho_i = act([h, z_i, dz_i] @ Wp^T + bp) -> smem RHO + global
__device__ __forceinline__ void project(int node, const float* z, const float* dz,
                                        float* rho_g, bool isfwd, bool hz, int row0)
{
    extern __shared__ float sm[];
    const int t = threadIdx.x;
    if (t < 2 * ROWS * SEX) {
        int which = t / 40;          // 0: z, 1: dz
        int loc = t % 40;
        int b = loc / SEX, u = loc % SEX;
        const float* src = which ? dz : z;
        sm[(which ? OFF_DZI : OFF_ZI) + loc] =
            src[((size_t)(row0 + b)) * NN * SEX + (size_t)node * SEX + u];
    }
    __syncthreads();
    for (int idx = t; idx < SS * ROWS; idx += NT) {
        int o = idx >> 2, b = idx & 3;
        float acc = sm[OFF_BP + o];
        const float4* wrow = (const float4*)&sm[OFF_WP + o * 80];
        if (!hz) {
#pragma unroll
            for (int q = 0; q < SS / 4; q++) {
                float4 w4 = wrow[q];
                acc = fmaf(w4.x, sm[OFF_H4 + (4 * q + 0) * 4 + b], acc);
                acc = fmaf(w4.y, sm[OFF_H4 + (4 * q + 1) * 4 + b], acc);
                acc = fmaf(w4.z, sm[OFF_H4 + (4 * q + 2) * 4 + b], acc);
                acc = fmaf(w4.w, sm[OFF_H4 + (4 * q + 3) * 4 + b], acc);
            }
        }
#pragma unroll
        for (int q = 0; q < (2 * SEX) / 4; q++) {
            float4 w4 = wrow[SS / 4 + q];
            int u = 4 * q;
            // cols 60..69 -> z, 70..79 -> dz
            float v0 = (u < SEX)     ? sm[OFF_ZI + b * SEX + u]           : sm[OFF_DZI + b * SEX + u - SEX];
            float v1 = (u + 1 < SEX) ? sm[OFF_ZI + b * SEX + u + 1]       : sm[OFF_DZI + b * SEX + u + 1 - SEX];
            float v2 = (u + 2 < SEX) ? sm[OFF_ZI + b * SEX + u + 2]       : sm[OFF_DZI + b * SEX + u + 2 - SEX];
            float v3 = (u + 3 < SEX) ? sm[OFF_ZI + b * SEX + u + 3]       : sm[OFF_DZI + b * SEX + u + 3 - SEX];
            acc = fmaf(w4.x, v0, acc);
            acc = fmaf(w4.y, v1, acc);
            acc = fmaf(w4.z, v2, acc);
            acc = fmaf(w4.w, v3, acc);
        }
        float v = isfwd ? tanh_f(acc) : acc;
        sm[OFF_RHO + idx] = v;
        rho_g[((size_t)node * BATCH + row0 + b) * SS + o] = v;
    }
    __syncthreads();
}

// gi[node] = rho[node] @ Wih^T + bih
__device__ __forceinline__ void gi_step(int node, float* gi_g, int row0)
{
    extern __shared__ float sm[];
    const int t = threadIdx.x;
    if (t < GG) {
        unsigned long long a01 = splat2(sm[OFF_BIH + t]);
        unsigned long long a23 = a01;
        const float4* wrow = (const float4*)&sm[OFF_WIH + t * SS];
#pragma unroll
        for (int q = 0; q < SS / 4; q++) {
            float4 w4 = wrow[q];
            ulonglong2 r0 = *(const ulonglong2*)&sm[OFF_RHO + (4 * q + 0) * 4];
            ulonglong2 r1 = *(const ulonglong2*)&sm[OFF_RHO + (4 * q + 1) * 4];
            ulonglong2 r2 = *(const ulonglong2*)&sm[OFF_RHO + (4 * q + 2) * 4];
            ulonglong2 r3 = *(const ulonglong2*)&sm[OFF_RHO + (4 * q + 3) * 4];
            unsigned long long wx = splat2(w4.x), wy = splat2(w4.y);
            unsigned long long wz = splat2(w4.z), ww = splat2(w4.w);
            fma2(a01, wx, r0.x); fma2(a23, wx, r0.y);
            fma2(a01, wy, r1.x); fma2(a23, wy, r1.y);
            fma2(a01, wz, r2.x); fma2(a23, wz, r2.y);
            fma2(a01, ww, r3.x); fma2(a23, ww, r3.y);
        }
        float* gb = gi_g + ((size_t)node * BATCH + row0) * GG + t;
        gb[0] = lo32(a01);
        gb[GG] = hi32(a01);
        gb[2 * GG] = lo32(a23);
        gb[3 * GG] = hi32(a23);
    }
    __syncthreads();
}

__global__ void __launch_bounds__(NT, 2)
phase1_kernel(const float* z, const float* dz, const float* has, const int* adj,
              const float* Wih_f, const float* Whh_f, const float* bih_f, const float* bhh_f,
              const float* Wih_b, const float* Whh_b, const float* bih_b, const float* bhh_b,
              const float* Wf, const float* bf, const float* Wb, const float* bb)
{
    extern __shared__ float sm[];
    const int t = threadIdx.x;
    const int row0 = blockIdx.x * ROWS;
    const int dir = blockIdx.y;          // 0 = fwd, 1 = bwd

    const float* Whh = dir ? Whh_b : Whh_f;
    const float* Wih = dir ? Wih_b : Wih_f;
    const float* Wp  = dir ? Wb    : Wf;
    const float* bhh = dir ? bhh_b : bhh_f;
    const float* bih = dir ? bih_b : bih_f;
    const float* bp  = dir ? bb    : bf;
    float* rho_g = dir ? g_rho_b : g_rho_f;
    float* gi_g  = dir ? g_gi_b  : g_gi_f;
    float* alpha_g = dir ? g_alpha_b : g_alpha_f;

    // ---- stage weights (row-major), biases, has, masks ----
    for (int idx = t; idx < GG * SS; idx += NT) {
        sm[OFF_WHH + idx] = Whh[idx];
        sm[OFF_WIH + idx] = Wih[idx];
    }
    for (int idx = t; idx < SS * (SS + 2 * SEX); idx += NT) sm[OFF_WP + idx] = Wp[idx];
    for (int idx = t; idx < GG; idx += NT) {
        sm[OFF_BHH + idx] = bhh[idx];
        sm[OFF_BIH + idx] = bih[idx];
    }
    if (t < SS) sm[OFF_BP + t] = bp[t];
    for (int idx = t; idx < ROWS * NN; idx += NT)
        sm[OFF_HAS + idx] = has[(size_t)(row0 + idx / NN) * NN + (idx % NN)];
    if (t < NN) {
        unsigned long long pm = 0ull, sk = 0ull;
        for (int j = 0; j < NN; j++) {
            if (adj[j * NN + t]) pm |= 1ull << j;   // predecessors of t
            if (adj[t * NN + j]) sk |= 1ull << j;   // successors of t
        }
        ((unsigned long long*)&sm[OFF_MASK])[t] = dir ? sk : pm;
        bool need = dir ? (pm != 0ull || t < II) : (sk != 0ull || t >= NN - OO);
        ((int*)&sm[OFF_NEED])[t] = need ? 1 : 0;
    }
    __syncthreads();

    const unsigned long long* mask = (const unsigned long long*)&sm[OFF_MASK];
    const int* need = (const int*)&sm[OFF_NEED];

    // ---- DAG pass ----
    for (int k = 0; k < NN; k++) {
        const int i = dir ? NN - 1 - k : k;
        bool hz = true;
        unsigned long long m = mask[i];
        while (m) {
            int j;
            if (dir) { j = 63 - __clzll((long long)m); m &= ~(1ull << j); }   // descending
            else     { j = __ffsll((long long)m) - 1;  m &= m - 1; }          // ascending
            gru_step(j, gi_g, hz, row0);
        }
        project(i, z, dz, rho_g, dir == 0, hz, row0);
        if (need[i]) gi_step(i, gi_g, row0);
    }

    // ---- alpha scan ----
    {
        bool hz = true;
        for (int k = 0; k < OO; k++) {
            int an = dir ? (II - 1 - k) : (NN - OO + k);
            gru_step(an, gi_g, hz, row0);
        }
        for (int idx = t; idx < SS * ROWS; idx += NT) {
            int o = idx >> 2, b = idx & 3;
            alpha_g[(size_t)(row0 + b) * SS + o] = sm[OFF_H4 + idx];
        }
    }
}

// ---- phase 2: heads + psi + softmaxes ----
#define P2_AF 0
#define P2_AB 240
#define P2_WU 480
#define P2_HAS 1320
#define P2_OMG 1576
#define P2_PSI 1600
#define P2_FLOATS (1600 + ROWS * NROLE * NN)

__global__ void __launch_bounds__(NT)
phase2_kernel(const float* has, const float* Wa, const float* ba,
              const float* Wc, const float* bc, const float* Wu, const float* bu,
              float* out)
{
    __shared__ float s2[P2_FLOATS];
    const int t = threadIdx.x;
    const int row0 = blockIdx.x * ROWS;

    for (int idx = t; idx < SS * ROWS; idx += NT) {
        int s = idx >> 2, b = idx & 3;
        s2[P2_AF + idx] = g_alpha_f[(size_t)(row0 + b) * SS + s];
        s2[P2_AB + idx] = g_alpha_b[(size_t)(row0 + b) * SS + s];
    }
    for (int idx = t; idx < NROLE * 2 * SS; idx += NT) s2[P2_WU + idx] = Wu[idx];
    for (int idx = t; idx < ROWS * NN; idx += NT)
        s2[P2_HAS + idx] = has[(size_t)(row0 + idx / NN) * NN + (idx % NN)];
    __syncthreads();

    if (t < ROWS * NACT) {
        int b = t / NACT, a = t % NACT;
        float acc = ba[a];
#pragma unroll
        for (int s = 0; s < SS; s++) {
            acc = fmaf(Wa[a * 2 * SS + s],      s2[P2_AF + s * 4 + b], acc);
            acc = fmaf(Wa[a * 2 * SS + SS + s], s2[P2_AB + s * 4 + b], acc);
        }
        s2[P2_OMG + t] = acc;
    } else if (t < ROWS * NACT + ROWS) {
        int b = t - ROWS * NACT;
        float acc = bc[0];
#pragma unroll
        for (int s = 0; s < SS; s++) {
            acc = fmaf(Wc[s],      s2[P2_AF + s * 4 + b], acc);
            acc = fmaf(Wc[SS + s], s2[P2_AB + s * 4 + b], acc);
        }
        out[(size_t)BATCH * NACT + (size_t)BATCH * NROLE * NN + row0 + b] = acc;
    }
    __syncthreads();
    if (t < ROWS) {
        float mx = -1e30f;
        for (int a = 0; a < NACT; a++) mx = fmaxf(mx, s2[P2_OMG + t * NACT + a]);
        float e[NACT], ssum = 0.f;
        for (int a = 0; a < NACT; a++) {
            e[a] = __expf(s2[P2_OMG + t * NACT + a] - mx);
            ssum += e[a];
        }
        float inv = __fdividef(1.f, ssum);
        for (int a = 0; a < NACT; a++) out[(size_t)(row0 + t) * NACT + a] = e[a] * inv;
    }

    // psi: warp-reduced dots
    {
        int warp = t >> 5, lane = t & 31;
        for (int it = warp; it < ROWS * NROLE * NN; it += NT / 32) {
            int n = it % NN;
            int r = (it / NN) % NROLE;
            int b = it / (NROLE * NN);
            const float* rf = g_rho_f + ((size_t)n * BATCH + row0 + b) * SS;
            const float* rb = g_rho_b + ((size_t)n * BATCH + row0 + b) * SS;
            float p = 0.f;
            for (int s = lane; s < SS; s += 32)
                p += rf[s] * s2[P2_WU + r * 2 * SS + s] + rb[s] * s2[P2_WU + r * 2 * SS + SS + s];
#pragma unroll
            for (int o2 = 16; o2; o2 >>= 1) p += __shfl_xor_sync(0xffffffffu, p, o2);
            if (lane == 0) {
                float mval = s2[P2_HAS + b * NN + n];
                float v = p + bu[r];
                v = mval * v - 60.f * (1.f - mval);
                s2[P2_PSI + (b * NROLE + r) * NN + n] = v;
            }
        }
    }
    __syncthreads();
    for (int p0 = t; p0 < ROWS * NROLE; p0 += NT) {
        int b = p0 / NROLE, r = p0 % NROLE;
        float* rowp = &s2[P2_PSI + (b * NROLE + r) * NN];
        float mx = -1e30f;
        for (int n = 0; n < NN; n++) mx = fmaxf(mx, rowp[n]);
        float ssum = 0.f;
        for (int n = 0; n < NN; n++) { float e = __expf(rowp[n] - mx); rowp[n] = e; ssum += e; }
        float inv = __fdividef(1.f, ssum);
        float* op = out + (size_t)BATCH * NACT + (size_t)(row0 + b) * NROLE * NN + (size_t)r * NN;
        for (int n = 0; n < NN; n++) op[n] = rowp[n] * inv;
    }
}

extern "C" void kernel_launch(void* const* d_in, const int* in_sizes, int n_in,
                              void* d_out, int out_size)
{
    cudaFuncSetAttribute(phase1_kernel, cudaFuncAttributeMaxDynamicSharedMemorySize, SMEM_BYTES);
    dim3 grid1(BATCH / ROWS, 2);
    phase1_kernel<<<grid1, NT, SMEM_BYTES>>>(
        (const float*)d_in[0], (const float*)d_in[1], (const float*)d_in[2], (const int*)d_in[3],
        (const float*)d_in[4], (const float*)d_in[5], (const float*)d_in[6], (const float*)d_in[7],
        (const float*)d_in[8], (const float*)d_in[9], (const float*)d_in[10], (const float*)d_in[11],
        (const float*)d_in[12], (const float*)d_in[13], (const float*)d_in[14], (const float*)d_in[15]);
    phase2_kernel<<<BATCH / ROWS, NT>>>(
        (const float*)d_in[2],
        (const float*)d_in[16], (const float*)d_in[17], (const float*)d_in[18], (const float*)d_in[19],
        (const float*)d_in[20], (const float*)d_in[21], (float*)d_out);
}